// round 7
// baseline (speedup 1.0000x reference)
#include <cuda_runtime.h>
#include <cuda_fp16.h>
#include <cstdint>

#define CDIM 256
#define MAX_ROWS 32768
#define MAX_KCB  4096

#define M_TILE 128
#define N_CHUNK 256
#define KT 64                 // halfs per k-window (= 128 B per row)
#define ROWB 128
#define THREADS 512

// smem layout (occ 1): A-resident 8 subtiles (comp*4+kc), then 3 B stages, red
#define SM_A    0
#define ASUB    16384                       // 128 rows * 128 B
#define SM_B    (8 * ASUB)                  // 131072
#define BSTG    (N_CHUNK * ROWB)            // 32768
#define NBUF    3
#define SM_RED  (SM_B + NBUF * BSTG)        // 229376
#define SMEM_TOTAL (SM_RED + 128 * 8)       // 230400 <= 232448

// ---------------- device globals ----------------
__device__ int    g_idx[MAX_ROWS];
__device__ float  g_e2[MAX_KCB];
__device__ float  g_partial[MAX_ROWS];
__device__ __half g_x0[MAX_ROWS * CDIM];
__device__ __half g_x1[MAX_ROWS * CDIM];
__device__ __half g_c0[MAX_KCB * CDIM];
__device__ __half g_c1[MAX_KCB * CDIM];

// ---------------- PTX helpers ----------------
__device__ __forceinline__ uint32_t smem_u32(const void* p) {
    uint32_t a;
    asm("{ .reg .u64 t; cvta.to.shared.u64 t, %1; cvt.u32.u64 %0, t; }"
        : "=r"(a) : "l"(p));
    return a;
}

#define CP_ASYNC16(dst, src) \
    asm volatile("cp.async.cg.shared.global [%0], [%1], 16;" :: "r"(dst), "l"(src))
#define CP_COMMIT()  asm volatile("cp.async.commit_group;")
#define CP_WAIT1()   asm volatile("cp.async.wait_group 1;")
#define CP_WAIT0()   asm volatile("cp.async.wait_group 0;")

#define LDSM_X4(r0, r1, r2, r3, addr)                                          \
    asm volatile("ldmatrix.sync.aligned.m8n8.x4.shared.b16 {%0,%1,%2,%3}, [%4];" \
        : "=r"(r0), "=r"(r1), "=r"(r2), "=r"(r3) : "r"(addr))

#define MMA16816(d, a0, a1, a2, a3, b0, b1)                                    \
    asm volatile("mma.sync.aligned.m16n8k16.row.col.f32.f16.f16.f32 "          \
        "{%0,%1,%2,%3},{%4,%5,%6,%7},{%8,%9},{%0,%1,%2,%3};"                   \
        : "+f"((d)[0]), "+f"((d)[1]), "+f"((d)[2]), "+f"((d)[3])               \
        : "r"(a0), "r"(a1), "r"(a2), "r"(a3), "r"(b0), "r"(b1))

// ---------------------------------------------------------------------------
__global__ void split_kernel(const float* __restrict__ src,
                             __half* __restrict__ d0,
                             __half* __restrict__ d1, int n) {
    int i = blockIdx.x * blockDim.x + threadIdx.x;
    if (i >= n) return;
    float v = src[i];
    __half h0 = __float2half_rn(v);
    float r = v - __half2float(h0);
    d0[i] = h0;
    d1[i] = __float2half_rn(r);
}

__global__ void e2_kernel(const float* __restrict__ cb, int kcb) {
    int w = (blockIdx.x * blockDim.x + threadIdx.x) >> 5;
    int lane = threadIdx.x & 31;
    if (w >= kcb) return;
    const float4* p = (const float4*)(cb + (size_t)w * CDIM);
    float s = 0.f;
    #pragma unroll
    for (int i = lane; i < CDIM / 4; i += 32) {
        float4 v = p[i];
        s += v.x * v.x + v.y * v.y + v.z * v.z + v.w * v.w;
    }
    #pragma unroll
    for (int o = 16; o; o >>= 1) s += __shfl_xor_sync(0xffffffffu, s, o);
    if (lane == 0) g_e2[w] = s;
}

// ---------------------------------------------------------------------------
// A-resident HMMA GEMM + argmin. 512 threads = 16 warps as 2(m) x 8(n),
// warp tile 64x32, N_CHUNK=256. A (h0,h1: 128KB) loaded once; B streamed in
// 32KB stages; each (c0,kc) B stage feeds two passes (A-h0, A-h1).
// ---------------------------------------------------------------------------
__global__ void __launch_bounds__(THREADS, 1)
mma_argmin_kernel(int kcb) {
    extern __shared__ char smem[];
    const uint32_t sb = smem_u32(smem);
    const int tid = threadIdx.x;
    const int wid = tid >> 5, lane = tid & 31;
    const int warp_m = wid & 1, warp_n = wid >> 1;     // 2 x 8
    const int rowBase = blockIdx.x * M_TILE;
    const int nChunks = kcb / N_CHUNK;            // 4
    const int S = nChunks * 8;                    // 32 B-stages

    // ---- A preload: 8 subtiles (comp*4+kc), swizzled 128B rows ----
    {
        #pragma unroll
        for (int st = 0; st < 8; st++) {
            const int comp = st >> 2, kc = st & 3;
            const __half* xa = comp ? g_x1 : g_x0;
            const char* asrc = (const char*)(xa + (size_t)rowBase * CDIM + kc * KT);
            const uint32_t ab = sb + SM_A + st * ASUB;
            #pragma unroll
            for (int i = 0; i < 2; i++) {              // 1024 units / 512 thr
                int u = tid + THREADS * i;
                int r = u >> 3, q = u & 7;
                CP_ASYNC16(ab + r * ROWB + ((q ^ (r & 7)) * 16),
                           asrc + (size_t)r * (CDIM * 2) + q * 16);
            }
        }
        CP_COMMIT();
    }

    // ---- B stage loader: s -> (chunk, kc, which) ----
    auto load_B = [&](int s) {
        const int c = s >> 3, w = s & 7;
        const int kc = w >> 1, which = w & 1;
        const __half* cbp = which ? g_c1 : g_c0;
        const char* bsrc = (const char*)(cbp + (size_t)(c * N_CHUNK) * CDIM + kc * KT);
        const uint32_t bb = sb + SM_B + (s % NBUF) * BSTG;
        #pragma unroll
        for (int i = 0; i < 4; i++) {                  // 2048 units / 512 thr
            int u = tid + THREADS * i;
            int r = u >> 3, q = u & 7;
            CP_ASYNC16(bb + r * ROWB + ((q ^ (r & 7)) * 16),
                       bsrc + (size_t)r * (CDIM * 2) + q * 16);
        }
        CP_COMMIT();
    };

    load_B(0);
    load_B(1);

    // ldmatrix address components
    const int lrow = lane & 15;
    const int hi   = lane >> 4;
    const int xorl = lrow & 7;
    uint32_t arow[4], brow[2];
    #pragma unroll
    for (int mt = 0; mt < 4; mt++)
        arow[mt] = (warp_m * 64 + mt * 16 + lrow) * ROWB;
    #pragma unroll
    for (int p = 0; p < 2; p++)
        brow[p] = (warp_n * 32 + p * 16 + lrow) * ROWB;

    float acc[4][4][4];
    #pragma unroll
    for (int mt = 0; mt < 4; mt++)
        #pragma unroll
        for (int nt = 0; nt < 4; nt++)
            #pragma unroll
            for (int e = 0; e < 4; e++) acc[mt][nt][e] = 0.f;

    float best[8];
    int   bidx[8];
    #pragma unroll
    for (int i = 0; i < 8; i++) { best[i] = 3.4e38f; bidx[i] = 0; }

    // one MMA pass: A subtile (comp,kc) x current B stage
    auto pass = [&](int comp, int kc, uint32_t bb) {
        const uint32_t ab = sb + SM_A + (comp * 4 + kc) * ASUB;
        #pragma unroll
        for (int ks = 0; ks < 4; ks++) {
            const uint32_t koff = ((uint32_t)((ks * 2 + hi) ^ xorl)) * 16;
            uint32_t ar[4][4];
            uint32_t br[4][2];
            #pragma unroll
            for (int mt = 0; mt < 4; mt++)
                LDSM_X4(ar[mt][0], ar[mt][1], ar[mt][2], ar[mt][3],
                        ab + arow[mt] + koff);
            #pragma unroll
            for (int p = 0; p < 2; p++) {
                uint32_t r0, r1, r2, r3;
                LDSM_X4(r0, r1, r2, r3, bb + brow[p] + koff);
                br[2 * p][0] = r0; br[2 * p][1] = r2;
                br[2 * p + 1][0] = r1; br[2 * p + 1][1] = r3;
            }
            #pragma unroll
            for (int mt = 0; mt < 4; mt++)
                #pragma unroll
                for (int nt = 0; nt < 4; nt++)
                    MMA16816(acc[mt][nt],
                             ar[mt][0], ar[mt][1], ar[mt][2], ar[mt][3],
                             br[nt][0], br[nt][1]);
        }
    };

    for (int s = 0; s < S; s++) {
        if (s == S - 1) CP_WAIT0(); else CP_WAIT1();
        __syncthreads();
        if (s + 2 < S) load_B(s + 2);

        const int w = s & 7;
        const int kc = w >> 1, which = w & 1;
        const uint32_t bb = sb + SM_B + (s % NBUF) * BSTG;

        pass(0, kc, bb);
        if (which == 0) pass(1, kc, bb);      // c0 stage also feeds A-h1

        // ---- chunk epilogue ----
        if (w == 7) {
            const int c = s >> 3;
            const int colBase = c * N_CHUNK + warp_n * 32 + (lane & 3) * 2;
            #pragma unroll
            for (int nt = 0; nt < 4; nt++) {
                const int n0 = colBase + nt * 8;
                float2 e2v = *(const float2*)&g_e2[n0];
                #pragma unroll
                for (int mt = 0; mt < 4; mt++) {
                    float s0 = e2v.x - 2.f * acc[mt][nt][0];
                    float s1 = e2v.y - 2.f * acc[mt][nt][1];
                    float s2 = e2v.x - 2.f * acc[mt][nt][2];
                    float s3 = e2v.y - 2.f * acc[mt][nt][3];
                    int h0 = mt * 2, h1 = mt * 2 + 1;
                    if (s0 < best[h0]) { best[h0] = s0; bidx[h0] = n0; }
                    if (s1 < best[h0]) { best[h0] = s1; bidx[h0] = n0 + 1; }
                    if (s2 < best[h1]) { best[h1] = s2; bidx[h1] = n0; }
                    if (s3 < best[h1]) { best[h1] = s3; bidx[h1] = n0 + 1; }
                    acc[mt][nt][0] = acc[mt][nt][1] = 0.f;
                    acc[mt][nt][2] = acc[mt][nt][3] = 0.f;
                }
            }
        }
    }

    // ---- final cross-thread argmin via packed smem atomicMin ----
    unsigned long long* red = (unsigned long long*)(smem + SM_RED);
    __syncthreads();
    for (int i = tid; i < M_TILE; i += THREADS) red[i] = 0xFFFFFFFFFFFFFFFFull;
    __syncthreads();
    #pragma unroll
    for (int slot = 0; slot < 8; slot++) {
        int mt = slot >> 1, h = slot & 1;
        int rl = warp_m * 64 + mt * 16 + (lane >> 2) + h * 8;
        uint32_t fb = __float_as_uint(best[slot]);
        uint32_t key = fb ^ ((fb & 0x80000000u) ? 0xFFFFFFFFu : 0x80000000u);
        unsigned long long pk =
            ((unsigned long long)key << 32) | (unsigned long long)(uint32_t)bidx[slot];
        atomicMin(&red[rl], pk);
    }
    __syncthreads();
    if (tid < M_TILE)
        g_idx[rowBase + tid] = (int)(red[tid] & 0xFFFFFFFFu);
}

// ---------------------------------------------------------------------------
__global__ void gather_kernel(const float* __restrict__ x,
                              const float* __restrict__ cbk,
                              float* __restrict__ outq,
                              float* __restrict__ outidx) {
    int row = blockIdx.x;
    int t = threadIdx.x;   // 64
    int idx = g_idx[row];

    float4 q  = *(const float4*)(cbk + (size_t)idx * CDIM + t * 4);
    float4 xv = *(const float4*)(x   + (size_t)row * CDIM + t * 4);
    *(float4*)(outq + (size_t)row * CDIM + t * 4) = q;

    float dx = q.x - xv.x, dy = q.y - xv.y, dz = q.z - xv.z, dw = q.w - xv.w;
    float s = dx * dx + dy * dy + dz * dz + dw * dw;
    #pragma unroll
    for (int o = 16; o; o >>= 1) s += __shfl_xor_sync(0xffffffffu, s, o);

    __shared__ float sh[2];
    if ((t & 31) == 0) sh[t >> 5] = s;
    __syncthreads();
    if (t == 0) {
        g_partial[row] = sh[0] + sh[1];
        if (outidx) outidx[row] = (float)idx;
    }
}

__global__ void finalize_kernel(float* __restrict__ outloss, int rows, int qn) {
    __shared__ double sh[1024];
    double s = 0.0;
    for (int i = threadIdx.x; i < rows; i += 1024) s += (double)g_partial[i];
    sh[threadIdx.x] = s;
    __syncthreads();
    for (int st = 512; st; st >>= 1) {
        if (threadIdx.x < st) sh[threadIdx.x] += sh[threadIdx.x + st];
        __syncthreads();
    }
    if (threadIdx.x == 0)
        *outloss = (float)(1.25 * sh[0] / (double)qn);
}

// ---------------------------------------------------------------------------
extern "C" void kernel_launch(void* const* d_in, const int* in_sizes, int n_in,
                              void* d_out, int out_size) {
    const float* x  = (const float*)d_in[0];
    const float* cb = (const float*)d_in[1];
    float* out = (float*)d_out;

    const int qn   = in_sizes[0];          // 8*4096*256
    const int kcb  = in_sizes[1] / CDIM;   // 1024
    const int rows = qn / CDIM;            // 32768

    __half *px0, *px1, *pc0, *pc1;
    cudaGetSymbolAddress((void**)&px0, g_x0);
    cudaGetSymbolAddress((void**)&px1, g_x1);
    cudaGetSymbolAddress((void**)&pc0, g_c0);
    cudaGetSymbolAddress((void**)&pc1, g_c1);

    split_kernel<<<(qn + 255) / 256, 256>>>(x, px0, px1, qn);
    split_kernel<<<(kcb * CDIM + 255) / 256, 256>>>(cb, pc0, pc1, kcb * CDIM);
    e2_kernel<<<(kcb * 32 + 255) / 256, 256>>>(cb, kcb);

    cudaFuncSetAttribute(mma_argmin_kernel,
                         cudaFuncAttributeMaxDynamicSharedMemorySize, SMEM_TOTAL);
    mma_argmin_kernel<<<rows / M_TILE, THREADS, SMEM_TOTAL>>>(kcb);

    bool has_loss = out_size >= qn + 1;
    bool has_idx  = out_size >= qn + 1 + rows;
    float* outidx = has_idx ? (out + qn + 1) : nullptr;

    gather_kernel<<<rows, 64>>>(x, cb, out, outidx);
    if (has_loss)
        finalize_kernel<<<1, 1024>>>(out + qn, rows, qn);
}

// round 8
// speedup vs baseline: 1.0943x; 1.0943x over previous
#include <cuda_runtime.h>
#include <cuda_fp16.h>
#include <cstdint>

#define CDIM 256
#define MAX_ROWS 32768
#define MAX_KCB  4096

#define M_TILE 128
#define N_CHUNK 256
#define KT 64                 // halfs per k-window (= 128 B per row)
#define ROWB 128
#define THREADS 256

// smem layout (occ 1): A-resident 8 subtiles (comp*4+kc), then 3 B stages, red
#define SM_A    0
#define ASUB    16384                       // 128 rows * 128 B
#define SM_B    (8 * ASUB)                  // 131072
#define BSTG    (N_CHUNK * ROWB)            // 32768
#define NBUF    3
#define SM_RED  (SM_B + NBUF * BSTG)        // 229376
#define SMEM_TOTAL (SM_RED + 128 * 8)       // 230400 <= 232448

// ---------------- device globals ----------------
__device__ int    g_idx[MAX_ROWS];
__device__ float  g_e2[MAX_KCB];
__device__ float  g_partial[MAX_ROWS];
__device__ float  g_x2s[MAX_ROWS];
__device__ __half g_c0[MAX_KCB * CDIM];
__device__ __half g_c1[MAX_KCB * CDIM];

// ---------------- PTX helpers ----------------
__device__ __forceinline__ uint32_t smem_u32(const void* p) {
    uint32_t a;
    asm("{ .reg .u64 t; cvta.to.shared.u64 t, %1; cvt.u32.u64 %0, t; }"
        : "=r"(a) : "l"(p));
    return a;
}

#define CP_ASYNC16(dst, src) \
    asm volatile("cp.async.cg.shared.global [%0], [%1], 16;" :: "r"(dst), "l"(src))
#define CP_COMMIT()  asm volatile("cp.async.commit_group;")
#define CP_WAIT1()   asm volatile("cp.async.wait_group 1;")
#define CP_WAIT0()   asm volatile("cp.async.wait_group 0;")

#define LDSM_X4(r0, r1, r2, r3, addr)                                          \
    asm volatile("ldmatrix.sync.aligned.m8n8.x4.shared.b16 {%0,%1,%2,%3}, [%4];" \
        : "=r"(r0), "=r"(r1), "=r"(r2), "=r"(r3) : "r"(addr))

#define MMA16816(d, a0, a1, a2, a3, b0, b1)                                    \
    asm volatile("mma.sync.aligned.m16n8k16.row.col.f32.f16.f16.f32 "          \
        "{%0,%1,%2,%3},{%4,%5,%6,%7},{%8,%9},{%0,%1,%2,%3};"                   \
        : "+f"((d)[0]), "+f"((d)[1]), "+f"((d)[2]), "+f"((d)[3])               \
        : "r"(a0), "r"(a1), "r"(a2), "r"(a3), "r"(b0), "r"(b1))

// ---------------------------------------------------------------------------
// split: fp32 -> 2 fp16 components (codebook only now)
// ---------------------------------------------------------------------------
__global__ void split_kernel(const float* __restrict__ src,
                             __half* __restrict__ d0,
                             __half* __restrict__ d1, int n) {
    int i = blockIdx.x * blockDim.x + threadIdx.x;
    if (i >= n) return;
    float v = src[i];
    __half h0 = __float2half_rn(v);
    float r = v - __half2float(h0);
    d0[i] = h0;
    d1[i] = __float2half_rn(r);
}

// ---------------------------------------------------------------------------
// e2[k] = ||codebook_k||^2 ; also used as x2 per-row kernel (same shape math)
// ---------------------------------------------------------------------------
__global__ void rownorm_kernel(const float* __restrict__ src,
                               float* __restrict__ dst, int rows) {
    int w = (blockIdx.x * blockDim.x + threadIdx.x) >> 5;
    int lane = threadIdx.x & 31;
    if (w >= rows) return;
    const float4* p = (const float4*)(src + (size_t)w * CDIM);
    float s = 0.f;
    #pragma unroll
    for (int i = lane; i < CDIM / 4; i += 32) {
        float4 v = p[i];
        s += v.x * v.x + v.y * v.y + v.z * v.z + v.w * v.w;
    }
    #pragma unroll
    for (int o = 16; o; o >>= 1) s += __shfl_xor_sync(0xffffffffu, s, o);
    if (lane == 0) dst[w] = s;
}

// ---------------------------------------------------------------------------
// A-resident HMMA GEMM + argmin. 256 threads = 8 warps as 2(m) x 4(n),
// warp tile 64x64. A split on the fly (fp32 LDG -> h0/h1 -> STS).
// c0 stages: B frags loaded once, fused h0+h1 MMA passes into same acc.
// Epilogue writes g_partial = x2 + best_score (loss needs no re-gather).
// ---------------------------------------------------------------------------
__global__ void __launch_bounds__(THREADS, 1)
mma_argmin_kernel(const float* __restrict__ x, int kcb) {
    extern __shared__ char smem[];
    const uint32_t sb = smem_u32(smem);
    const int tid = threadIdx.x;
    const int wid = tid >> 5, lane = tid & 31;
    const int warp_m = wid & 1, warp_n = wid >> 1;     // 2 x 4
    const int rowBase = blockIdx.x * M_TILE;
    const int nChunks = kcb / N_CHUNK;            // 4
    const int S = nChunks * 8;                    // 32 B-stages

    // ---- B stage loader ----
    auto load_B = [&](int s) {
        const int c = s >> 3, w = s & 7;
        const int kc = w >> 1, which = w & 1;
        const __half* cbp = which ? g_c1 : g_c0;
        const char* bsrc = (const char*)(cbp + (size_t)(c * N_CHUNK) * CDIM + kc * KT);
        const uint32_t bb = sb + SM_B + (s % NBUF) * BSTG;
        #pragma unroll
        for (int i = 0; i < 8; i++) {
            int u = tid + THREADS * i;
            int r = u >> 3, q = u & 7;
            CP_ASYNC16(bb + r * ROWB + ((q ^ (r & 7)) * 16),
                       bsrc + (size_t)r * (CDIM * 2) + q * 16);
        }
        CP_COMMIT();
    };

    load_B(0);
    load_B(1);

    // ---- on-the-fly A split: fp32 -> h0 (subtiles 0..3), h1 (4..7) ----
    {
        const float* xsrc = x + (size_t)rowBase * CDIM;
        #pragma unroll 4
        for (int i = 0; i < 32; i++) {
            int u = tid + THREADS * i;          // float4 index
            int row = u >> 6;
            int coloff = (u & 63) * 4;          // 0..252
            float4 v = *(const float4*)(xsrc + (size_t)row * CDIM + coloff);
            float f0 = v.x, f1 = v.y, f2 = v.z, f3 = v.w;
            __half a0 = __float2half_rn(f0), a1 = __float2half_rn(f1);
            __half a2 = __float2half_rn(f2), a3 = __float2half_rn(f3);
            __half b0 = __float2half_rn(f0 - __half2float(a0));
            __half b1 = __float2half_rn(f1 - __half2float(a1));
            __half b2 = __float2half_rn(f2 - __half2float(a2));
            __half b3 = __float2half_rn(f3 - __half2float(a3));
            int kc = coloff >> 6;
            int c  = coloff & 63;
            uint32_t off = (uint32_t)row * ROWB +
                           ((uint32_t)(((c >> 3) ^ (row & 7))) * 16) + ((c & 7) * 2);
            __half2 h0lo = __halves2half2(a0, a1), h0hi = __halves2half2(a2, a3);
            __half2 h1lo = __halves2half2(b0, b1), h1hi = __halves2half2(b2, b3);
            uint32_t d0 = sb + SM_A + kc * ASUB + off;
            uint32_t d1 = sb + SM_A + (4 + kc) * ASUB + off;
            asm volatile("st.shared.v2.b32 [%0], {%1,%2};" ::
                "r"(d0), "r"(*(uint32_t*)&h0lo), "r"(*(uint32_t*)&h0hi));
            asm volatile("st.shared.v2.b32 [%0], {%1,%2};" ::
                "r"(d1), "r"(*(uint32_t*)&h1lo), "r"(*(uint32_t*)&h1hi));
        }
    }

    // ldmatrix address components
    const int lrow = lane & 15;
    const int hi   = lane >> 4;
    const int xorl = lrow & 7;
    uint32_t arow[4], brow[4];
    #pragma unroll
    for (int mt = 0; mt < 4; mt++)
        arow[mt] = (warp_m * 64 + mt * 16 + lrow) * ROWB;
    #pragma unroll
    for (int p = 0; p < 4; p++)
        brow[p] = (warp_n * 64 + p * 16 + lrow) * ROWB;

    float acc[4][8][4];
    #pragma unroll
    for (int mt = 0; mt < 4; mt++)
        #pragma unroll
        for (int nt = 0; nt < 8; nt++)
            #pragma unroll
            for (int e = 0; e < 4; e++) acc[mt][nt][e] = 0.f;

    float best[8];
    int   bidx[8];
    #pragma unroll
    for (int i = 0; i < 8; i++) { best[i] = 3.4e38f; bidx[i] = 0; }

    // single pass (h0 x c1 stages)
    auto pass = [&](int kc, uint32_t bb) {
        const uint32_t ab = sb + SM_A + kc * ASUB;
        #pragma unroll
        for (int ks = 0; ks < 4; ks++) {
            const uint32_t koff = ((uint32_t)((ks * 2 + hi) ^ xorl)) * 16;
            uint32_t ar[4][4];
            uint32_t br[8][2];
            #pragma unroll
            for (int p = 0; p < 4; p++) {
                uint32_t r0, r1, r2, r3;
                LDSM_X4(r0, r1, r2, r3, bb + brow[p] + koff);
                br[2 * p][0] = r0; br[2 * p][1] = r2;
                br[2 * p + 1][0] = r1; br[2 * p + 1][1] = r3;
            }
            #pragma unroll
            for (int mt = 0; mt < 4; mt++)
                LDSM_X4(ar[mt][0], ar[mt][1], ar[mt][2], ar[mt][3],
                        ab + arow[mt] + koff);
            #pragma unroll
            for (int mt = 0; mt < 4; mt++)
                #pragma unroll
                for (int nt = 0; nt < 8; nt++)
                    MMA16816(acc[mt][nt],
                             ar[mt][0], ar[mt][1], ar[mt][2], ar[mt][3],
                             br[nt][0], br[nt][1]);
        }
    };

    // fused pass (h0 and h1 vs same B, c0 stages): B frags loaded once
    auto pass2 = [&](int kc, uint32_t bb) {
        const uint32_t ab0 = sb + SM_A + kc * ASUB;
        const uint32_t ab1 = sb + SM_A + (4 + kc) * ASUB;
        #pragma unroll
        for (int ks = 0; ks < 4; ks++) {
            const uint32_t koff = ((uint32_t)((ks * 2 + hi) ^ xorl)) * 16;
            uint32_t br[8][2];
            #pragma unroll
            for (int p = 0; p < 4; p++) {
                uint32_t r0, r1, r2, r3;
                LDSM_X4(r0, r1, r2, r3, bb + brow[p] + koff);
                br[2 * p][0] = r0; br[2 * p][1] = r2;
                br[2 * p + 1][0] = r1; br[2 * p + 1][1] = r3;
            }
            uint32_t ar0[4][4], ar1[4][4];
            #pragma unroll
            for (int mt = 0; mt < 4; mt++)
                LDSM_X4(ar0[mt][0], ar0[mt][1], ar0[mt][2], ar0[mt][3],
                        ab0 + arow[mt] + koff);
            #pragma unroll
            for (int mt = 0; mt < 4; mt++)
                LDSM_X4(ar1[mt][0], ar1[mt][1], ar1[mt][2], ar1[mt][3],
                        ab1 + arow[mt] + koff);
            #pragma unroll
            for (int mt = 0; mt < 4; mt++)
                #pragma unroll
                for (int nt = 0; nt < 8; nt++)
                    MMA16816(acc[mt][nt],
                             ar0[mt][0], ar0[mt][1], ar0[mt][2], ar0[mt][3],
                             br[nt][0], br[nt][1]);
            #pragma unroll
            for (int mt = 0; mt < 4; mt++)
                #pragma unroll
                for (int nt = 0; nt < 8; nt++)
                    MMA16816(acc[mt][nt],
                             ar1[mt][0], ar1[mt][1], ar1[mt][2], ar1[mt][3],
                             br[nt][0], br[nt][1]);
        }
    };

    for (int s = 0; s < S; s++) {
        if (s == S - 1) CP_WAIT0(); else CP_WAIT1();
        __syncthreads();
        if (s + 2 < S) load_B(s + 2);

        const int w = s & 7;
        const int kc = w >> 1, which = w & 1;
        const uint32_t bb = sb + SM_B + (s % NBUF) * BSTG;

        if (which == 0) pass2(kc, bb);
        else            pass(kc, bb);

        // ---- chunk epilogue ----
        if (w == 7) {
            const int c = s >> 3;
            const int colBase = c * N_CHUNK + warp_n * 64 + (lane & 3) * 2;
            #pragma unroll
            for (int nt = 0; nt < 8; nt++) {
                const int n0 = colBase + nt * 8;
                float2 e2v = *(const float2*)&g_e2[n0];
                #pragma unroll
                for (int mt = 0; mt < 4; mt++) {
                    float s0 = e2v.x - 2.f * acc[mt][nt][0];
                    float s1 = e2v.y - 2.f * acc[mt][nt][1];
                    float s2 = e2v.x - 2.f * acc[mt][nt][2];
                    float s3 = e2v.y - 2.f * acc[mt][nt][3];
                    int h0 = mt * 2, h1 = mt * 2 + 1;
                    if (s0 < best[h0]) { best[h0] = s0; bidx[h0] = n0; }
                    if (s1 < best[h0]) { best[h0] = s1; bidx[h0] = n0 + 1; }
                    if (s2 < best[h1]) { best[h1] = s2; bidx[h1] = n0; }
                    if (s3 < best[h1]) { best[h1] = s3; bidx[h1] = n0 + 1; }
                    acc[mt][nt][0] = acc[mt][nt][1] = 0.f;
                    acc[mt][nt][2] = acc[mt][nt][3] = 0.f;
                }
            }
        }
    }

    // ---- final cross-thread argmin via packed smem atomicMin ----
    unsigned long long* red = (unsigned long long*)(smem + SM_RED);
    __syncthreads();
    for (int i = tid; i < M_TILE; i += THREADS) red[i] = 0xFFFFFFFFFFFFFFFFull;
    __syncthreads();
    #pragma unroll
    for (int slot = 0; slot < 8; slot++) {
        int mt = slot >> 1, h = slot & 1;
        int rl = warp_m * 64 + mt * 16 + (lane >> 2) + h * 8;
        uint32_t fb = __float_as_uint(best[slot]);
        uint32_t key = fb ^ ((fb & 0x80000000u) ? 0xFFFFFFFFu : 0x80000000u);
        unsigned long long pk =
            ((unsigned long long)key << 32) | (unsigned long long)(uint32_t)bidx[slot];
        atomicMin(&red[rl], pk);
    }
    __syncthreads();
    if (tid < M_TILE) {
        unsigned long long pk = red[tid];
        uint32_t key = (uint32_t)(pk >> 32);
        uint32_t fb = (key & 0x80000000u) ? (key ^ 0x80000000u) : ~key;
        int row = rowBase + tid;
        g_idx[row] = (int)(pk & 0xFFFFFFFFu);
        g_partial[row] = g_x2s[row] + __uint_as_float(fb);   // = dist^2
    }
}

// ---------------------------------------------------------------------------
// gather: pure codebook gather + index write (loss already in g_partial)
// ---------------------------------------------------------------------------
__global__ void gather_kernel(const float* __restrict__ cbk,
                              float* __restrict__ outq,
                              float* __restrict__ outidx) {
    int row = blockIdx.x;
    int t = threadIdx.x;   // 64
    int idx = g_idx[row];
    float4 q = *(const float4*)(cbk + (size_t)idx * CDIM + t * 4);
    *(float4*)(outq + (size_t)row * CDIM + t * 4) = q;
    if (t == 0 && outidx) outidx[row] = (float)idx;
}

__global__ void finalize_kernel(float* __restrict__ outloss, int rows, int qn) {
    __shared__ double sh[1024];
    const float4* p4 = (const float4*)g_partial;
    double s = 0.0;
    for (int i = threadIdx.x; i < rows / 4; i += 1024) {
        float4 v = p4[i];
        s += (double)v.x + (double)v.y + (double)v.z + (double)v.w;
    }
    sh[threadIdx.x] = s;
    __syncthreads();
    for (int st = 512; st; st >>= 1) {
        if (threadIdx.x < st) sh[threadIdx.x] += sh[threadIdx.x + st];
        __syncthreads();
    }
    if (threadIdx.x == 0)
        *outloss = (float)(1.25 * sh[0] / (double)qn);
}

// ---------------------------------------------------------------------------
extern "C" void kernel_launch(void* const* d_in, const int* in_sizes, int n_in,
                              void* d_out, int out_size) {
    const float* x  = (const float*)d_in[0];
    const float* cb = (const float*)d_in[1];
    float* out = (float*)d_out;

    const int qn   = in_sizes[0];          // 8*4096*256
    const int kcb  = in_sizes[1] / CDIM;   // 1024
    const int rows = qn / CDIM;            // 32768

    __half *pc0, *pc1;
    float *pe2, *px2;
    cudaGetSymbolAddress((void**)&pc0, g_c0);
    cudaGetSymbolAddress((void**)&pc1, g_c1);
    cudaGetSymbolAddress((void**)&pe2, g_e2);
    cudaGetSymbolAddress((void**)&px2, g_x2s);

    split_kernel<<<(kcb * CDIM + 255) / 256, 256>>>(cb, pc0, pc1, kcb * CDIM);
    rownorm_kernel<<<(kcb * 32 + 255) / 256, 256>>>(cb, pe2, kcb);
    rownorm_kernel<<<(rows * 32 + 255) / 256, 256>>>(x, px2, rows);

    cudaFuncSetAttribute(mma_argmin_kernel,
                         cudaFuncAttributeMaxDynamicSharedMemorySize, SMEM_TOTAL);
    mma_argmin_kernel<<<rows / M_TILE, THREADS, SMEM_TOTAL>>>(x, kcb);

    bool has_loss = out_size >= qn + 1;
    bool has_idx  = out_size >= qn + 1 + rows;
    float* outidx = has_idx ? (out + qn + 1) : nullptr;

    gather_kernel<<<rows, 64>>>(cb, out, outidx);
    if (has_loss)
        finalize_kernel<<<1, 1024>>>(out + qn, rows, qn);
}